// round 14
// baseline (speedup 1.0000x reference)
#include <cuda_runtime.h>
#include <cuda_bf16.h>
#include <cstdint>
#include <cstddef>

// ---------------------------------------------------------------------------
// MultiCELoss: KL(softmax(scores) || softmax(cos(anchor,tgt)))/(R-1) mean
//            + ALPHA * mean_b( lse_j(scale * a_b . t_j) - scale * a_b . t_b )
// B=4096, R=18, D=256.  Heavy part: 4096 x 69632 x 256 bf16 mma.sync GEMM
// fused with per-row online logsumexp.  R12 ncu: tensor=52.6%, occ=12.5%
// (2 warps/SMSP) -> latency-bound, not issue-bound.  This round: 512 threads
// (16 warps, 4/SMSP), warp tile 32x32, same 128x128 CTA tile + smem layout.
// Deterministic: no float atomics; fixed reduction trees.
// ---------------------------------------------------------------------------

#define C_ALPHA 0.2f
#define C_BETA  1.0f
#define C_EPS   1e-8f

#define MAXB 4096
#define MAXR 18
#define DD   256
#define NSPLIT 32
#define NMT   32          // B/BM mtiles

__device__ __align__(16) __nv_bfloat16 g_anchor[(size_t)MAXB * DD];   // pre-scaled by logit_scale
__device__ __align__(16) __nv_bfloat16 g_targets[(size_t)MAXB * (MAXR - 1) * DD];
__device__ float g_diag[MAXB];       // raw anchor.pos dot (unscaled)
__device__ float g_kl[MAXB];
__device__ float g_part_m[(size_t)NSPLIT * MAXB];
__device__ float g_part_l[(size_t)NSPLIT * MAXB];
__device__ float g_msum[NMT];
__device__ int   g_cnt[NMT + 1];     // [0..NMT-1] per-mtile, [NMT] final

// ---------------------------------------------------------------------------
// PTX helpers
// ---------------------------------------------------------------------------
__device__ __forceinline__ void cp_async16(uint32_t saddr, const void* gaddr) {
    asm volatile("cp.async.cg.shared.global [%0], [%1], 16;\n"
                 :: "r"(saddr), "l"(gaddr) : "memory");
}
__device__ __forceinline__ void cp_commit() {
    asm volatile("cp.async.commit_group;\n" ::: "memory");
}
template <int N>
__device__ __forceinline__ void cp_wait() {
    asm volatile("cp.async.wait_group %0;\n" :: "n"(N) : "memory");
}
__device__ __forceinline__ void ldsm4(uint32_t* r, uint32_t addr) {
    asm volatile("ldmatrix.sync.aligned.m8n8.x4.shared.b16 {%0,%1,%2,%3}, [%4];\n"
                 : "=r"(r[0]), "=r"(r[1]), "=r"(r[2]), "=r"(r[3]) : "r"(addr));
}
__device__ __forceinline__ void mma16816(float* c, const uint32_t* a, uint32_t b0, uint32_t b1) {
    asm volatile("mma.sync.aligned.m16n8k16.row.col.f32.bf16.bf16.f32 "
                 "{%0,%1,%2,%3}, {%4,%5,%6,%7}, {%8,%9}, {%0,%1,%2,%3};\n"
                 : "+f"(c[0]), "+f"(c[1]), "+f"(c[2]), "+f"(c[3])
                 : "r"(a[0]), "r"(a[1]), "r"(a[2]), "r"(a[3]), "r"(b0), "r"(b1));
}

// ---------------------------------------------------------------------------
// Kernel 1 (prep): one pass over features.  grid=B, block=R*32 (18 warps).
// Warp k: dot(anchor,row k) + |row k|^2, then bf16 convert+reorder (anchor
// pre-scaled by logit_scale).  Warp 0 then computes KL + diag.  Block 0 also
// re-zeroes the completion counters for this replay.
// ---------------------------------------------------------------------------
__global__ void prep_kernel(const float* __restrict__ f,
                            const float* __restrict__ scores,
                            const float* __restrict__ lscale,
                            int B, int R, int D) {
    int b = blockIdx.x;
    int warp = threadIdx.x >> 5, lane = threadIdx.x & 31;
    int k = warp;                     // 0..R-1
    __shared__ float s_dot[32], s_nrm[32];

    if (b == 0 && threadIdx.x <= NMT) g_cnt[threadIdx.x] = 0;

    const float4* xr = (const float4*)(f + ((size_t)b * R + k) * D);
    const float4* ar = (const float4*)(f + (size_t)b * R * D);
    float4 x0 = xr[2 * lane], x1 = xr[2 * lane + 1];
    float4 a0 = ar[2 * lane], a1 = ar[2 * lane + 1];

    float dp = a0.x*x0.x + a0.y*x0.y + a0.z*x0.z + a0.w*x0.w
             + a1.x*x1.x + a1.y*x1.y + a1.z*x1.z + a1.w*x1.w;
    float sq = x0.x*x0.x + x0.y*x0.y + x0.z*x0.z + x0.w*x0.w
             + x1.x*x1.x + x1.y*x1.y + x1.z*x1.z + x1.w*x1.w;
    #pragma unroll
    for (int o = 16; o > 0; o >>= 1) {
        dp += __shfl_xor_sync(0xffffffffu, dp, o);
        sq += __shfl_xor_sync(0xffffffffu, sq, o);
    }
    if (lane == 0) { s_dot[k] = dp; s_nrm[k] = sq; }

    // bf16 conversion + reorder (anchor scaled by logit_scale)
    {
        float sc = (k == 0) ? __ldg(lscale) : 1.0f;
        __nv_bfloat16* dst;
        if (k == 0)      dst = g_anchor  + (size_t)b * D;
        else if (k == 1) dst = g_targets + (size_t)b * D;
        else             dst = g_targets + ((size_t)B + (size_t)b * (R - 2) + (k - 2)) * D;
        union { __nv_bfloat162 h[4]; uint4 u; } cv;
        cv.h[0] = __floats2bfloat162_rn(sc * x0.x, sc * x0.y);
        cv.h[1] = __floats2bfloat162_rn(sc * x0.z, sc * x0.w);
        cv.h[2] = __floats2bfloat162_rn(sc * x1.x, sc * x1.y);
        cv.h[3] = __floats2bfloat162_rn(sc * x1.z, sc * x1.w);
        ((uint4*)dst)[lane] = cv.u;
    }
    __syncthreads();

    if (warp == 0) {
        int kk = lane;
        bool valid = (kk >= 1 && kk < R);
        int ki = valid ? kk : 1;
        float an   = fmaxf(sqrtf(s_nrm[0]), C_EPS);
        float cosv = valid ? s_dot[ki] / (an * fmaxf(sqrtf(s_nrm[ki]), C_EPS)) : -1e30f;
        float scv  = valid ? scores[(size_t)b * (R - 1) + (kk - 1)] : -1e30f;

        float cmax = cosv, smax = scv;
        #pragma unroll
        for (int o = 16; o > 0; o >>= 1) {
            cmax = fmaxf(cmax, __shfl_xor_sync(0xffffffffu, cmax, o));
            smax = fmaxf(smax, __shfl_xor_sync(0xffffffffu, smax, o));
        }
        float c_e  = valid ? __expf(cosv - cmax) : 0.f;
        float ce_e = valid ? __expf(scv  - smax) : 0.f;
        float csum = c_e, ssum = ce_e;
        #pragma unroll
        for (int o = 16; o > 0; o >>= 1) {
            csum += __shfl_xor_sync(0xffffffffu, csum, o);
            ssum += __shfl_xor_sync(0xffffffffu, ssum, o);
        }
        float emb_log = cosv - cmax - logf(csum);
        float lce     = scv  - smax - logf(ssum);
        float ce      = ce_e / ssum;
        float term    = valid ? ce * (lce - emb_log) : 0.f;
        #pragma unroll
        for (int o = 16; o > 0; o >>= 1)
            term += __shfl_xor_sync(0xffffffffu, term, o);
        if (lane == 0) {
            g_kl[b]   = term / (float)(R - 1);
            g_diag[b] = s_dot[1];
        }
    }
}

// ---------------------------------------------------------------------------
// Kernel 2: fused GEMM + online logsumexp + deterministic merge/final tail.
// BM=BN=128, K=256.  16 warps (4x4); warp tile 32x32 (2 A-LDSM + 2 B-LDSM,
// 8 MMA per k-step); 2-stage k register pipeline; A resident; B
// double-buffered cp.async; 528B padded smem stride.
// ---------------------------------------------------------------------------
#define BM 128
#define BN 128
#define NTHREADS 512
#define SSTRIDE 528
#define TILE_SMEM (128 * SSTRIDE)    // 67584 B
#define GEMM_SMEM (3 * TILE_SMEM)    // A + 2x B = 202752 B

__device__ __forceinline__ void load_tile_async(uint32_t sbase,
                                                const __nv_bfloat16* gsrc,
                                                int tid) {
    const char* src = (const char*)gsrc;
    #pragma unroll
    for (int i = 0; i < 8; i++) {
        int c   = i * NTHREADS + tid;   // 4096 x 16B chunks
        int row = c >> 5, col = c & 31;
        cp_async16(sbase + row * SSTRIDE + col * 16, src + row * 512 + col * 16);
    }
    cp_commit();
}

__global__ __launch_bounds__(NTHREADS, 1)
void gemm_lse_kernel(const float* __restrict__ logit_scale_ptr,
                     float* __restrict__ out, int B, int ntiles) {
    extern __shared__ char smem[];
    const int tid  = threadIdx.x;
    const int warp = tid >> 5, lane = tid & 31;
    const int split = blockIdx.x;      // 0..NSPLIT-1
    const int mtile = blockIdx.y;      // 0..NMT-1

    const uint32_t As_b  = (uint32_t)__cvta_generic_to_shared(smem);
    const uint32_t Bs_b0 = As_b + TILE_SMEM;
    const uint32_t Bs_b1 = As_b + 2 * TILE_SMEM;

    // work partition over N tiles (544 total -> 17 per split)
    int tps = ntiles / NSPLIT, rem = ntiles % NSPLIT;
    int my_nt = tps + (split < rem ? 1 : 0);
    int tbase = split * tps + (split < rem ? split : rem);

    // A tile (anchors, pre-scaled) — stays resident
    load_tile_async(As_b, g_anchor + (size_t)mtile * BM * DD, tid);
    if (my_nt > 0)
        load_tile_async(Bs_b0, g_targets + (size_t)(tbase)*BN * DD, tid);

    const int q = lane >> 3;
    const int wrow = warp & 3;        // A row block (32 rows)
    const int wcol = warp >> 2;       // B col block (32 cols), 0..3
    const uint32_t a_off = (uint32_t)((wrow * 32 + (lane & 7) + (q & 1) * 8) * SSTRIDE
                                      + (q >> 1) * 16);
    const uint32_t b_off = (uint32_t)((wcol * 32 + (lane & 7) + (q >> 1) * 8) * SSTRIDE
                                      + (q & 1) * 16);

    float m4[4] = {-1e30f, -1e30f, -1e30f, -1e30f};
    float l4[4] = {0.f, 0.f, 0.f, 0.f};

    for (int i = 0; i < my_nt; i++) {
        if (i + 1 < my_nt)
            load_tile_async((i & 1) ? Bs_b0 : Bs_b1,
                            g_targets + (size_t)(tbase + i + 1) * BN * DD, tid);
        if (i + 1 < my_nt) cp_wait<1>(); else cp_wait<0>();
        __syncthreads();

        const uint32_t Bb = (i & 1) ? Bs_b1 : Bs_b0;
        float c[2][4][4];
        #pragma unroll
        for (int mi = 0; mi < 2; mi++)
            #pragma unroll
            for (int ni = 0; ni < 4; ni++) {
                c[mi][ni][0] = 0.f; c[mi][ni][1] = 0.f;
                c[mi][ni][2] = 0.f; c[mi][ni][3] = 0.f;
            }

        // 2-stage register pipeline over the 16 k-steps
        uint32_t af[2][2][4], bf[2][2][4];
        ldsm4(af[0][0], As_b + a_off);
        ldsm4(af[0][1], As_b + a_off + 16 * SSTRIDE);
        ldsm4(bf[0][0], Bb + b_off);
        ldsm4(bf[0][1], Bb + b_off + 16 * SSTRIDE);

        #pragma unroll
        for (int k = 0; k < 16; k++) {
            const int s = k & 1;
            if (k < 15) {
                const int ss = s ^ 1;
                const uint32_t ko = (uint32_t)((k + 1) * 32);
                ldsm4(af[ss][0], As_b + a_off + ko);
                ldsm4(af[ss][1], As_b + a_off + 16 * SSTRIDE + ko);
                ldsm4(bf[ss][0], Bb + b_off + ko);
                ldsm4(bf[ss][1], Bb + b_off + 16 * SSTRIDE + ko);
            }
            #pragma unroll
            for (int mi = 0; mi < 2; mi++)
                #pragma unroll
                for (int nj = 0; nj < 2; nj++) {
                    mma16816(c[mi][2 * nj],     af[s][mi], bf[s][nj][0], bf[s][nj][1]);
                    mma16816(c[mi][2 * nj + 1], af[s][mi], bf[s][nj][2], bf[s][nj][3]);
                }
        }

        // ---- online logsumexp (logits already scaled via anchors)
        float vmax[4];
        #pragma unroll
        for (int g = 0; g < 4; g++) {
            const int mi = g >> 1, h = g & 1;
            float vm = -1e30f;
            #pragma unroll
            for (int ni = 0; ni < 4; ni++)
                vm = fmaxf(vm, fmaxf(c[mi][ni][2 * h], c[mi][ni][2 * h + 1]));
            vm = fmaxf(vm, __shfl_xor_sync(0xffffffffu, vm, 1));
            vm = fmaxf(vm, __shfl_xor_sync(0xffffffffu, vm, 2));
            vmax[g] = vm;
        }
        bool need = (vmax[0] > m4[0] - 25.f) || (vmax[1] > m4[1] - 25.f)
                 || (vmax[2] > m4[2] - 25.f) || (vmax[3] > m4[3] - 25.f);
        if (__ballot_sync(0xffffffffu, need)) {
            #pragma unroll
            for (int g = 0; g < 4; g++) {
                const int mi = g >> 1, h = g & 1;
                float nm = fmaxf(m4[g], vmax[g]);
                float s = 0.f;
                #pragma unroll
                for (int ni = 0; ni < 4; ni++)
                    s += __expf(c[mi][ni][2 * h] - nm) + __expf(c[mi][ni][2 * h + 1] - nm);
                s += __shfl_xor_sync(0xffffffffu, s, 1);
                s += __shfl_xor_sync(0xffffffffu, s, 2);
                l4[g] = l4[g] * __expf(m4[g] - nm) + s;
                m4[g] = nm;
            }
        }
        __syncthreads();
    }

    // ---- combine the four column-quarter warps (wcol 0..3) per row
    __shared__ float s_m[512], s_l[512];   // [wcol*128 + row_in_tile]
    if ((lane & 3) == 0) {
        #pragma unroll
        for (int g = 0; g < 4; g++) {
            const int mi = g >> 1, h = g & 1;
            int rloc = wrow * 32 + mi * 16 + (lane >> 2) + h * 8;
            s_m[wcol * 128 + rloc] = m4[g];
            s_l[wcol * 128 + rloc] = l4[g];
        }
    }
    __syncthreads();
    if (tid < 128) {
        float M = s_m[tid];
        #pragma unroll
        for (int w = 1; w < 4; w++) M = fmaxf(M, s_m[w * 128 + tid]);
        float L = 0.f;
        #pragma unroll
        for (int w = 0; w < 4; w++)
            L += s_l[w * 128 + tid] * __expf(s_m[w * 128 + tid] - M);
        int row = mtile * BM + tid;
        size_t o = (size_t)split * B + row;
        g_part_m[o] = M;
        g_part_l[o] = L;
    }
    __syncthreads();

    // ---- deterministic merge tail: last split-CTA of this mtile merges
    __shared__ int s_flag;
    if (tid == 0) {
        __threadfence();
        int old = atomicAdd(&g_cnt[mtile], 1);
        s_flag = (old == NSPLIT - 1) ? 1 : 0;
    }
    __syncthreads();
    if (!s_flag) return;
    __threadfence();   // acquire: see all splits' partials

    float scale = __ldg(logit_scale_ptr);
    float val = 0.f;
    if (tid < 128) {
        int row = mtile * BM + tid;
        float M = -1e30f;
        #pragma unroll
        for (int i = 0; i < NSPLIT; i++) M = fmaxf(M, g_part_m[(size_t)i * B + row]);
        float L = 0.f;
        #pragma unroll
        for (int i = 0; i < NSPLIT; i++)
            L += g_part_l[(size_t)i * B + row] * __expf(g_part_m[(size_t)i * B + row] - M);
        float lse = M + logf(L);
        val = C_BETA * g_kl[row] + C_ALPHA * (lse - scale * g_diag[row]);
    }
    // fixed-tree reduce (threads 128..511 contribute 0)
    __shared__ float s_red[NTHREADS];
    s_red[tid] = val;
    __syncthreads();
    #pragma unroll
    for (int s = NTHREADS / 2; s > 0; s >>= 1) {
        if (tid < s) s_red[tid] += s_red[tid + s];
        __syncthreads();
    }
    if (tid == 0) {
        g_msum[mtile] = s_red[0];
        __threadfence();
        int old = atomicAdd(&g_cnt[NMT], 1);
        if (old == NMT - 1) {
            __threadfence();
            float tot = 0.f;
            #pragma unroll
            for (int i = 0; i < NMT; i++) tot += g_msum[i];
            out[0] = tot / (float)B;
        }
    }
}

// ---------------------------------------------------------------------------
extern "C" void kernel_launch(void* const* d_in, const int* in_sizes, int n_in,
                              void* d_out, int out_size) {
    const float* features = (const float*)d_in[0];
    const float* scores   = (const float*)d_in[1];
    const float* lscale   = (const float*)d_in[3];
    float* out = (float*)d_out;

    int B   = in_sizes[2];
    int Rm1 = in_sizes[1] / B;
    int R   = Rm1 + 1;
    int D   = in_sizes[0] / (B * R);   // 256

    cudaFuncSetAttribute(gemm_lse_kernel,
                         cudaFuncAttributeMaxDynamicSharedMemorySize, GEMM_SMEM);

    // 1. fused prep: stats (KL/diag) + bf16 conversion (anchor pre-scaled)
    //    + completion-counter reset for this replay
    prep_kernel<<<B, R * 32>>>(features, scores, lscale, B, R, D);
    // 2. fused GEMM + online logsumexp + merge/final tail
    int ntiles = (B * Rm1) / BN;       // 544
    dim3 grid(NSPLIT, B / BM);         // (32, 32)
    gemm_lse_kernel<<<grid, NTHREADS, GEMM_SMEM>>>(lscale, out, B, ntiles);
}